// round 9
// baseline (speedup 1.0000x reference)
#include <cuda_runtime.h>
#include <stdint.h>

#define ROWLEN   8192
#define NT       1024
#define NPT      8              // ROWLEN / NT
#define NWARP    32
#define KSEL     128
#define NBIN     1024
#define T0BITS   0x3FF00000u    // 1.875f: count(x>=t0) ~ 249 +/- 16 per N(0,1) row
#define SHIFT1   11             // primary bins: width 2^11 ulps
#define ROWBYTES (ROWLEN * 4)
#define GRID     304            // persistent CTAs (2 per SM x 152 SMs)

// dynamic smem layout (bytes)
#define OFF_ROW0 0
#define OFF_ROW1 32768
#define OFF_HIST 65536
#define OFF_W    (OFF_HIST + NBIN * 4)
#define OFF_BC   (OFF_W + NWARP * 4)
#define OFF_MBAR (OFF_BC + 32)
#define SMEM_SZ  (OFF_MBAR + 16)

__device__ __forceinline__ uint32_t smem_u32(const void* p) {
    uint32_t a;
    asm("{ .reg .u64 t; cvta.to.shared.u64 t, %1; cvt.u32.u64 %0, t; }"
        : "=r"(a) : "l"(p));
    return a;
}
__device__ __forceinline__ void mbar_init(uint32_t m, uint32_t c) {
    asm volatile("mbarrier.init.shared.b64 [%0], %1;" :: "r"(m), "r"(c) : "memory");
}
__device__ __forceinline__ void mbar_expect_tx(uint32_t m, uint32_t bytes) {
    asm volatile("mbarrier.arrive.expect_tx.shared.b64 _, [%0], %1;"
                 :: "r"(m), "r"(bytes) : "memory");
}
__device__ __forceinline__ void bulk_g2s(uint32_t dst, const void* src,
                                         uint32_t bytes, uint32_t m) {
    asm volatile("cp.async.bulk.shared::cluster.global.mbarrier::complete_tx::bytes "
                 "[%0], [%1], %2, [%3];"
                 :: "r"(dst), "l"(src), "r"(bytes), "r"(m) : "memory");
}
__device__ __forceinline__ void mbar_wait(uint32_t m, uint32_t ph) {
    uint32_t done;
    do {
        asm volatile("{ .reg .pred p; "
                     "mbarrier.try_wait.parity.acquire.cta.shared::cta.b64 p, [%1], %2, 0x989680; "
                     "selp.b32 %0, 1, 0, p; }"
                     : "=r"(done) : "r"(m), "r"(ph) : "memory");
    } while (!done);
}

// Persistent per-row top-K of relu(x), double-buffered cp.async.bulk row
// streaming. Selection = pre-filtered (t0=1.875) 1024-bin histogram refinement
// in positive-float bit space; exact for arbitrary data. Threshold ties broken
// by LOWEST COLUMN INDEX (jax.lax.top_k rule) via deterministic block scan.
extern __shared__ unsigned char dsm[];
__global__ __launch_bounds__(NT, 2)
void topk_relu_kernel(const float* __restrict__ x, float* __restrict__ out,
                      int rows) {
    const int tid  = threadIdx.x;
    const int wid  = tid >> 5;
    const int lane = tid & 31;

    uint32_t* __restrict__ hist = (uint32_t*)(dsm + OFF_HIST);
    uint32_t* __restrict__ wsm  = (uint32_t*)(dsm + OFF_W);
    uint32_t* __restrict__ bc   = (uint32_t*)(dsm + OFF_BC);
    const uint32_t smbase = smem_u32(dsm);
    const uint32_t mb0 = smbase + OFF_MBAR, mb1 = smbase + OFF_MBAR + 8;
    const uint32_t rowa0 = smbase + OFF_ROW0, rowa1 = smbase + OFF_ROW1;

    hist[tid] = 0u;
    if (tid == 0) {
        mbar_init(mb0, 1u);
        mbar_init(mb1, 1u);
        int r0 = blockIdx.x;
        if (r0 < rows)        { mbar_expect_tx(mb0, ROWBYTES); bulk_g2s(rowa0, x + (size_t)r0 * ROWLEN, ROWBYTES, mb0); }
        if (r0 + GRID < rows) { mbar_expect_tx(mb1, ROWBYTES); bulk_g2s(rowa1, x + (size_t)(r0 + GRID) * ROWLEN, ROWBYTES, mb1); }
    }
    __syncthreads();

    uint32_t ph0 = 0, ph1 = 0;
    int buf = 0;

    for (int r = blockIdx.x; r < rows; r += GRID, buf ^= 1) {
        const uint32_t mb = buf ? mb1 : mb0;
        if (buf) { mbar_wait(mb, ph1); ph1 ^= 1; }
        else     { mbar_wait(mb, ph0); ph0 ^= 1; }

        // ---- smem -> registers; column order = (i, tid, e) ----
        const float4* __restrict__ rb4 =
            (const float4*)(dsm + (buf ? OFF_ROW1 : OFF_ROW0));
        float v[NPT];
        {
            float4 f0 = rb4[tid];
            float4 f1 = rb4[tid + NT];
            v[0] = f0.x; v[1] = f0.y; v[2] = f0.z; v[3] = f0.w;
            v[4] = f1.x; v[5] = f1.y; v[6] = f1.z; v[7] = f1.w;
        }

        // ==== selection ====
        uint32_t lo = T0BITS, rng = 0xFFFFFFFFu;
        int shift = SHIFT1;
        uint32_t above = 0u;
        bool clamped = true, first = true;
        uint32_t Tb = 1u, quota = 0u;
        int tie_path = 0;

        for (;;) {
            // ---- histogram ----
            if (first) {
                // clamped full-range window: no upper-bound test needed
#pragma unroll
                for (int j = 0; j < NPT; j++) {
                    uint32_t bu = (__float_as_uint(v[j]) - T0BITS) >> SHIFT1;
                    if (v[j] >= 1.875f)
                        atomicAdd(&hist[bu < NBIN - 1u ? bu : NBIN - 1u], 1u);
                }
            } else {
                const float lof = __uint_as_float(lo);
#pragma unroll
                for (int j = 0; j < NPT; j++) {
                    if (v[j] >= lof) {
                        uint32_t d = __float_as_uint(v[j]) - lo;
                        if (d < rng) {
                            uint32_t b = d >> shift;
                            if (b > NBIN - 1u) b = NBIN - 1u;
                            atomicAdd(&hist[b], 1u);
                        }
                    }
                }
            }
            __syncthreads();                     // B1: histogram complete

            if (first && tid == 0) {             // prefetch row r+2*GRID into this buffer
                int rn = r + 2 * GRID;           // (all copies done: B1 passed)
                if (rn < rows) {
                    mbar_expect_tx(mb, ROWBYTES);
                    bulk_g2s(buf ? rowa1 : rowa0, x + (size_t)rn * ROWLEN, ROWBYTES, mb);
                }
            }

            // ---- two-level suffix scan (bins descend as tid ascends) ----
            const int rb = NBIN - 1 - tid;       // bin owned by this thread
            const uint32_t h = hist[rb];
            hist[rb] = 0u;                       // re-zero for next use
            const uint32_t wtot = __reduce_add_sync(0xFFFFFFFFu, h);
            if (lane == 0) wsm[wid] = wtot;
            __syncthreads();                     // B2: warp totals ready

            uint32_t t = wsm[lane];
            uint32_t sc = t;
#pragma unroll
            for (int o = 1; o < 32; o <<= 1) {
                uint32_t u = __shfl_up_sync(0xFFFFFFFFu, sc, o);
                if (lane >= o) sc += u;
            }
            const uint32_t basew = (wid == 0) ? 0u
                                   : __shfl_sync(0xFFFFFFFFu, sc, wid - 1);
            const uint32_t total = __shfl_sync(0xFFFFFFFFu, sc, 31);

            int is_cross = 0;
            const uint32_t pre = above + basew;  // elems in bins above my warp's range
            if (pre < KSEL && pre + wtot >= KSEL) {   // crossing warp (warp-uniform)
                uint32_t incl = h;               // intra-warp suffix (bins desc w/ lane)
#pragma unroll
                for (int o = 1; o < 32; o <<= 1) {
                    uint32_t u = __shfl_up_sync(0xFFFFFFFFu, incl, o);
                    if (lane >= o) incl += u;
                }
                const uint32_t suf = pre + incl;
                if (suf >= KSEL && suf - h < KSEL) {
                    bc[0] = (uint32_t)rb;
                    bc[1] = suf - h;             // count(bits >= crossing-bin end)
                    bc[2] = h;
                    is_cross = 1;
                }
            }
            const int found = __syncthreads_or(is_cross);   // B3

            if (!found) {
                if (first) {                     // count(>= t0) < K: search (0, t0)
                    above = total;
                    lo = 1u; rng = T0BITS - 1u; shift = 20;
                    clamped = false; first = false;
                    continue;
                }
                Tb = 1u; tie_path = 0; break;    // <K positives: output = relu(x)
            }
            first = false;
            const uint32_t bstar = bc[0];
            above = bc[1];
            const uint32_t hb = bc[2];
            const uint32_t rk = KSEL - above;    // rank within bin, 1 <= rk <= hb
            lo += bstar << shift;
            if (rk == hb) { Tb = lo; tie_path = 0; break; }  // whole bin => K
            if (shift == 0) { Tb = lo; quota = rk; tie_path = 1; break; }
            if (clamped && bstar == NBIN - 1u) {
                rng = 0xFFFFFFFFu; shift = 20; clamped = false;  // reopen clamp bin
            } else {
                rng = 1u << shift;
                shift = (shift > 10) ? (shift - 10) : 0;
                clamped = false;
            }
        }

        // ==== output straight from registers ====
        float4* __restrict__ ov = reinterpret_cast<float4*>(out + (size_t)r * ROWLEN);
        const float T = __uint_as_float(Tb);

        if (!tie_path) {
            float4 o0, o1;
            o0.x = (v[0] >= T) ? v[0] : 0.0f;
            o0.y = (v[1] >= T) ? v[1] : 0.0f;
            o0.z = (v[2] >= T) ? v[2] : 0.0f;
            o0.w = (v[3] >= T) ? v[3] : 0.0f;
            o1.x = (v[4] >= T) ? v[4] : 0.0f;
            o1.y = (v[5] >= T) ? v[5] : 0.0f;
            o1.z = (v[6] >= T) ? v[6] : 0.0f;
            o1.w = (v[7] >= T) ? v[7] : 0.0f;
            ov[tid]      = o0;
            ov[tid + NT] = o1;
        } else {
            // duplicates straddle rank K: keep `quota` lowest-index ties.
            uint32_t tc0 = 0, tc1 = 0;
            bool tie[NPT];
#pragma unroll
            for (int e = 0; e < 4; e++) { tie[e]   = (v[e]   == T); tc0 += tie[e]   ? 1u : 0u; }
#pragma unroll
            for (int e = 0; e < 4; e++) { tie[4+e] = (v[4+e] == T); tc1 += tie[4+e] ? 1u : 0u; }
            uint32_t packed = tc0 | (tc1 << 16);

            uint32_t incl = packed;
#pragma unroll
            for (int o = 1; o < 32; o <<= 1) {
                uint32_t u = __shfl_up_sync(0xFFFFFFFFu, incl, o);
                if (lane >= o) incl += u;
            }
            if (lane == 31) wsm[wid] = incl;
            __syncthreads();
            uint32_t t2 = wsm[lane];
            uint32_t sc2 = t2;
#pragma unroll
            for (int o = 1; o < 32; o <<= 1) {
                uint32_t u = __shfl_up_sync(0xFFFFFFFFu, sc2, o);
                if (lane >= o) sc2 += u;
            }
            uint32_t basew = (wid == 0) ? 0u
                             : __shfl_sync(0xFFFFFFFFu, sc2, wid - 1);
            uint32_t total0 = __shfl_sync(0xFFFFFFFFu, sc2, 31) & 0xFFFFu;
            const uint32_t excl = basew + incl - packed;

            uint32_t rank0 = excl & 0xFFFFu;
            uint32_t rank1 = total0 + (excl >> 16);

            float4 o0, o1; float a;
            a = v[0]; o0.x = (a > T) ? a : ((tie[0] && rank0++ < quota) ? a : 0.0f);
            a = v[1]; o0.y = (a > T) ? a : ((tie[1] && rank0++ < quota) ? a : 0.0f);
            a = v[2]; o0.z = (a > T) ? a : ((tie[2] && rank0++ < quota) ? a : 0.0f);
            a = v[3]; o0.w = (a > T) ? a : ((tie[3] && rank0++ < quota) ? a : 0.0f);
            a = v[4]; o1.x = (a > T) ? a : ((tie[4] && rank1++ < quota) ? a : 0.0f);
            a = v[5]; o1.y = (a > T) ? a : ((tie[5] && rank1++ < quota) ? a : 0.0f);
            a = v[6]; o1.z = (a > T) ? a : ((tie[6] && rank1++ < quota) ? a : 0.0f);
            a = v[7]; o1.w = (a > T) ? a : ((tie[7] && rank1++ < quota) ? a : 0.0f);
            ov[tid]      = o0;
            ov[tid + NT] = o1;
        }
    }
}

extern "C" void kernel_launch(void* const* d_in, const int* in_sizes, int n_in,
                              void* d_out, int out_size) {
    const float* x = (const float*)d_in[0];
    float* out = (float*)d_out;
    int rows = in_sizes[0] / ROWLEN;
    int grid = (rows < GRID) ? rows : GRID;
    cudaFuncSetAttribute(topk_relu_kernel,
                         cudaFuncAttributeMaxDynamicSharedMemorySize, SMEM_SZ);
    topk_relu_kernel<<<grid, NT, SMEM_SZ>>>(x, out, rows);
}

// round 10
// speedup vs baseline: 1.2477x; 1.2477x over previous
#include <cuda_runtime.h>
#include <stdint.h>

#define ROWLEN   8192
#define NT       1024
#define NPT      8              // ROWLEN / NT
#define NWARP    32
#define KSEL     128
#define NBIN     1024
#define T0BITS   0x3FF00000u    // 1.875f: count(x>=t0) ~ 249 +/- 16 per N(0,1) row
#define SHIFT1   11             // primary bins: width 2^11 ulps
#define ROWBYTES (ROWLEN * 4)
#define GRID     304            // persistent CTAs (2 per SM x 152 SMs)

__device__ __forceinline__ uint32_t smem_u32(const void* p) {
    uint32_t a;
    asm("{ .reg .u64 t; cvta.to.shared.u64 t, %1; cvt.u32.u64 %0, t; }"
        : "=r"(a) : "l"(p));
    return a;
}
__device__ __forceinline__ void mbar_init(uint32_t m, uint32_t c) {
    asm volatile("mbarrier.init.shared.b64 [%0], %1;" :: "r"(m), "r"(c) : "memory");
}
__device__ __forceinline__ void mbar_expect_tx(uint32_t m, uint32_t bytes) {
    asm volatile("mbarrier.arrive.expect_tx.shared.b64 _, [%0], %1;"
                 :: "r"(m), "r"(bytes) : "memory");
}
__device__ __forceinline__ void bulk_g2s(uint32_t dst, const void* src,
                                         uint32_t bytes, uint32_t m) {
    asm volatile("cp.async.bulk.shared::cluster.global.mbarrier::complete_tx::bytes "
                 "[%0], [%1], %2, [%3];"
                 :: "r"(dst), "l"(src), "r"(bytes), "r"(m) : "memory");
}
__device__ __forceinline__ void mbar_wait(uint32_t m, uint32_t ph) {
    uint32_t done;
    do {
        asm volatile("{ .reg .pred p; "
                     "mbarrier.try_wait.parity.acquire.cta.shared::cta.b64 p, [%1], %2; "
                     "selp.b32 %0, 1, 0, p; }"
                     : "=r"(done) : "r"(m), "r"(ph) : "memory");
    } while (!done);
}

struct SMem {
    float4   row[ROWLEN / 4];       // 32 KB staged row (written only by bulk copy)
    uint32_t hist[NBIN];            // 4 KB
    uint32_t w[NWARP];
    uint32_t bc[4];                 // 0=bstar 1=above_new 2=h 3=found
    unsigned long long mbar;
};

// Persistent per-row top-K of relu(x). Row r+GRID streams HBM->SMEM via
// cp.async.bulk while row r's selection runs. Selection = pre-filtered
// (t0=1.875) 1024-bin histogram refinement in positive-float bit space; exact
// for arbitrary data. Threshold ties broken by LOWEST COLUMN INDEX
// (jax.lax.top_k rule) via deterministic block scan.
__global__ __launch_bounds__(NT, 2)
void topk_relu_kernel(const float* __restrict__ x, float* __restrict__ out,
                      int rows) {
    __shared__ SMem sm;
    const int tid  = threadIdx.x;
    const int wid  = tid >> 5;
    const int lane = tid & 31;

    const uint32_t mb   = smem_u32(&sm.mbar);
    const uint32_t rowa = smem_u32(&sm.row[0]);

    sm.hist[tid] = 0u;
    if (tid == 0) mbar_init(mb, 1u);
    __syncthreads();

    int r = blockIdx.x;
    if (tid == 0 && r < rows)  // prologue prefetch
        { mbar_expect_tx(mb, ROWBYTES); bulk_g2s(rowa, x + (size_t)r * ROWLEN, ROWBYTES, mb); }
    uint32_t phase = 0;

    for (; r < rows; r += GRID) {
        mbar_wait(mb, phase); phase ^= 1;      // row r resident in smem

        // ---- smem -> registers; column order = (i, tid, e) ----
        float v[NPT];
        {
            float4 f0 = sm.row[tid];
            float4 f1 = sm.row[tid + NT];
            v[0] = f0.x; v[1] = f0.y; v[2] = f0.z; v[3] = f0.w;
            v[4] = f1.x; v[5] = f1.y; v[6] = f1.z; v[7] = f1.w;
        }
        // NOTE: no barrier here. B1 below orders all copies before the
        // prefetch that overwrites sm.row (copy precedes histogram per thread).

        // ==== selection: histogram refinement (bit space of positive floats) ====
        uint32_t lo = T0BITS, rng = 0xFFFFFFFFu;
        int shift = SHIFT1;
        uint32_t above = 0u;
        bool clamped = true, first = true;
        uint32_t Tb = 1u, quota = 0u;
        int tie_path = 0;

        for (;;) {
            // ---- histogram ----
            if (first) {
                // clamped full-range window: no upper-bound test needed
#pragma unroll
                for (int j = 0; j < NPT; j++) {
                    uint32_t bu = (__float_as_uint(v[j]) - T0BITS) >> SHIFT1;
                    if (v[j] >= 1.875f)
                        atomicAdd(&sm.hist[bu < NBIN - 1u ? bu : NBIN - 1u], 1u);
                }
            } else {
                const float lof = __uint_as_float(lo);
#pragma unroll
                for (int j = 0; j < NPT; j++) {
                    if (v[j] >= lof) {             // positive & bits >= lo
                        uint32_t d = __float_as_uint(v[j]) - lo;
                        if (d < rng) {
                            uint32_t b = d >> shift;
                            if (b > NBIN - 1u) b = NBIN - 1u;
                            atomicAdd(&sm.hist[b], 1u);
                        }
                    }
                }
            }
            __syncthreads();                   // B1: histogram complete (=> copies done)

            if (first && tid == 0) {           // prefetch row r+GRID (buffer now reusable)
                int rn = r + GRID;
                if (rn < rows) {
                    mbar_expect_tx(mb, ROWBYTES);
                    bulk_g2s(rowa, x + (size_t)rn * ROWLEN, ROWBYTES, mb);
                }
            }

            // ---- two-level suffix logic (bins descend as tid ascends) ----
            const int rb = NBIN - 1 - tid;
            const uint32_t h = sm.hist[rb];
            sm.hist[rb] = 0u;                  // re-zero for next use
            if (tid == 0) sm.bc[3] = 0u;
            const uint32_t wtot = __reduce_add_sync(0xFFFFFFFFu, h);
            if (lane == 0) sm.w[wid] = wtot;
            __syncthreads();                   // B2: warp totals ready

            // redundant per-warp scan of the 32 warp totals (no extra barrier)
            uint32_t t = sm.w[lane];
            uint32_t sc = t;
#pragma unroll
            for (int o = 1; o < 32; o <<= 1) {
                uint32_t u = __shfl_up_sync(0xFFFFFFFFu, sc, o);
                if (lane >= o) sc += u;
            }
            const uint32_t basew = (wid == 0) ? 0u
                                   : __shfl_sync(0xFFFFFFFFu, sc, wid - 1);
            const uint32_t total = __shfl_sync(0xFFFFFFFFu, sc, 31);

            const uint32_t pre = above + basew;     // elems above my warp's bin range
            if (pre < KSEL && pre + wtot >= KSEL) { // crossing warp only (uniform)
                uint32_t incl = h;             // intra-warp suffix (bins desc w/ lane)
#pragma unroll
                for (int o = 1; o < 32; o <<= 1) {
                    uint32_t u = __shfl_up_sync(0xFFFFFFFFu, incl, o);
                    if (lane >= o) incl += u;
                }
                const uint32_t suf = pre + incl;
                if (suf >= KSEL && suf - h < KSEL) {
                    sm.bc[0] = (uint32_t)rb;
                    sm.bc[1] = suf - h;        // count(bits >= crossing-bin end)
                    sm.bc[2] = h;
                    sm.bc[3] = 1u;
                }
            }
            __syncthreads();                   // B3: crossing published

            if (sm.bc[3] == 0u) {
                if (first) {                   // count(>= t0) < K: search (0, t0)
                    above = total;
                    lo = 1u; rng = T0BITS - 1u; shift = 20;
                    clamped = false; first = false;
                    continue;
                }
                Tb = 1u; tie_path = 0; break;  // <K positives: output = relu(x)
            }
            first = false;
            const uint32_t bstar = sm.bc[0];
            above = sm.bc[1];
            const uint32_t hb = sm.bc[2];
            const uint32_t rk = KSEL - above;  // rank within bin, 1 <= rk <= hb
            lo += bstar << shift;
            if (rk == hb) { Tb = lo; tie_path = 0; break; }   // whole bin => K
            if (shift == 0) { Tb = lo; quota = rk; tie_path = 1; break; }
            if (clamped && bstar == NBIN - 1u) {
                rng = 0xFFFFFFFFu; shift = 20; clamped = false;  // reopen clamp bin
            } else {
                rng = 1u << shift;
                shift = (shift > 10) ? (shift - 10) : 0;
                clamped = false;
            }
        }

        // ==== output straight from registers ====
        float4* __restrict__ ov = reinterpret_cast<float4*>(out + (size_t)r * ROWLEN);
        const float T = __uint_as_float(Tb);

        if (!tie_path) {
            float4 o0, o1;
            o0.x = (v[0] >= T) ? v[0] : 0.0f;
            o0.y = (v[1] >= T) ? v[1] : 0.0f;
            o0.z = (v[2] >= T) ? v[2] : 0.0f;
            o0.w = (v[3] >= T) ? v[3] : 0.0f;
            o1.x = (v[4] >= T) ? v[4] : 0.0f;
            o1.y = (v[5] >= T) ? v[5] : 0.0f;
            o1.z = (v[6] >= T) ? v[6] : 0.0f;
            o1.w = (v[7] >= T) ? v[7] : 0.0f;
            ov[tid]      = o0;
            ov[tid + NT] = o1;
        } else {
            // duplicates straddle rank K: keep `quota` lowest-index ties.
            uint32_t tc0 = 0, tc1 = 0;
            bool tie[NPT];
#pragma unroll
            for (int e = 0; e < 4; e++) { tie[e]   = (v[e]   == T); tc0 += tie[e]   ? 1u : 0u; }
#pragma unroll
            for (int e = 0; e < 4; e++) { tie[4+e] = (v[4+e] == T); tc1 += tie[4+e] ? 1u : 0u; }
            uint32_t packed = tc0 | (tc1 << 16);

            uint32_t incl = packed;
#pragma unroll
            for (int o = 1; o < 32; o <<= 1) {
                uint32_t u = __shfl_up_sync(0xFFFFFFFFu, incl, o);
                if (lane >= o) incl += u;
            }
            if (lane == 31) sm.w[wid] = incl;
            __syncthreads();
            uint32_t t2 = sm.w[lane];
            uint32_t sc2 = t2;
#pragma unroll
            for (int o = 1; o < 32; o <<= 1) {
                uint32_t u = __shfl_up_sync(0xFFFFFFFFu, sc2, o);
                if (lane >= o) sc2 += u;
            }
            uint32_t basew = (wid == 0) ? 0u
                             : __shfl_sync(0xFFFFFFFFu, sc2, wid - 1);
            uint32_t total0 = __shfl_sync(0xFFFFFFFFu, sc2, 31) & 0xFFFFu;
            const uint32_t excl = basew + incl - packed;

            uint32_t rank0 = excl & 0xFFFFu;
            uint32_t rank1 = total0 + (excl >> 16);

            float4 o0, o1; float a;
            a = v[0]; o0.x = (a > T) ? a : ((tie[0] && rank0++ < quota) ? a : 0.0f);
            a = v[1]; o0.y = (a > T) ? a : ((tie[1] && rank0++ < quota) ? a : 0.0f);
            a = v[2]; o0.z = (a > T) ? a : ((tie[2] && rank0++ < quota) ? a : 0.0f);
            a = v[3]; o0.w = (a > T) ? a : ((tie[3] && rank0++ < quota) ? a : 0.0f);
            a = v[4]; o1.x = (a > T) ? a : ((tie[4] && rank1++ < quota) ? a : 0.0f);
            a = v[5]; o1.y = (a > T) ? a : ((tie[5] && rank1++ < quota) ? a : 0.0f);
            a = v[6]; o1.z = (a > T) ? a : ((tie[6] && rank1++ < quota) ? a : 0.0f);
            a = v[7]; o1.w = (a > T) ? a : ((tie[7] && rank1++ < quota) ? a : 0.0f);
            ov[tid]      = o0;
            ov[tid + NT] = o1;
            __syncthreads();                   // protect sm.w before next row's reuse
        }
    }
}

extern "C" void kernel_launch(void* const* d_in, const int* in_sizes, int n_in,
                              void* d_out, int out_size) {
    const float* x = (const float*)d_in[0];
    float* out = (float*)d_out;
    int rows = in_sizes[0] / ROWLEN;
    int grid = (rows < GRID) ? rows : GRID;
    topk_relu_kernel<<<grid, NT>>>(x, out, rows);
}

// round 11
// speedup vs baseline: 1.2761x; 1.0228x over previous
#include <cuda_runtime.h>
#include <stdint.h>

#define ROWLEN   8192
#define NT       512
#define NPT      16             // ROWLEN / NT
#define NWARP    16
#define KSEL     128
#define NBIN     512            // one bin per thread
#define T0BITS   0x3FF00000u    // 1.875f: count(x>=t0) ~ 249 +/- 16 per N(0,1) row
#define SHIFT1   12             // primary bins: width 2^12 ulps (512 bins cover 2^21)
#define ROWBYTES (ROWLEN * 4)
#define GRID     608            // persistent CTAs (4 per SM x 152 SMs)

__device__ __forceinline__ uint32_t smem_u32(const void* p) {
    uint32_t a;
    asm("{ .reg .u64 t; cvta.to.shared.u64 t, %1; cvt.u32.u64 %0, t; }"
        : "=r"(a) : "l"(p));
    return a;
}
__device__ __forceinline__ void mbar_init(uint32_t m, uint32_t c) {
    asm volatile("mbarrier.init.shared.b64 [%0], %1;" :: "r"(m), "r"(c) : "memory");
}
__device__ __forceinline__ void mbar_expect_tx(uint32_t m, uint32_t bytes) {
    asm volatile("mbarrier.arrive.expect_tx.shared.b64 _, [%0], %1;"
                 :: "r"(m), "r"(bytes) : "memory");
}
__device__ __forceinline__ void bulk_g2s(uint32_t dst, const void* src,
                                         uint32_t bytes, uint32_t m) {
    asm volatile("cp.async.bulk.shared::cluster.global.mbarrier::complete_tx::bytes "
                 "[%0], [%1], %2, [%3];"
                 :: "r"(dst), "l"(src), "r"(bytes), "r"(m) : "memory");
}
__device__ __forceinline__ void mbar_wait(uint32_t m, uint32_t ph) {
    uint32_t done;
    do {
        asm volatile("{ .reg .pred p; "
                     "mbarrier.try_wait.parity.acquire.cta.shared::cta.b64 p, [%1], %2; "
                     "selp.b32 %0, 1, 0, p; }"
                     : "=r"(done) : "r"(m), "r"(ph) : "memory");
    } while (!done);
}

struct SMem {
    float4   row[ROWLEN / 4];       // 32 KB staged row (row data lives here, not regs)
    uint32_t hist[NBIN];            // 2 KB
    uint32_t w[2 * NWARP];          // scan scratch (two packed scans in tie path)
    uint32_t bc[4];                 // 0=bstar 1=above_new 2=h 3=found
    unsigned long long mbar;
};

// Persistent per-row top-K of relu(x). 4 CTAs/SM, each a small independent
// chain (load -> hist -> scan -> output); cross-CTA interleave hides barrier
// convoys and load latency. Row data stays in SMEM (re-read per phase) to keep
// regs <= 32 and occupancy at 4x512. Selection = pre-filtered (t0=1.875)
// 512-bin histogram refinement in positive-float bit space; exact for any
// input. Threshold ties broken by LOWEST COLUMN INDEX (jax.lax.top_k rule)
// via deterministic block scans.
__global__ __launch_bounds__(NT, 4)
void topk_relu_kernel(const float* __restrict__ x, float* __restrict__ out,
                      int rows) {
    __shared__ SMem sm;
    const int tid  = threadIdx.x;
    const int wid  = tid >> 5;
    const int lane = tid & 31;

    const uint32_t mb   = smem_u32(&sm.mbar);
    const uint32_t rowa = smem_u32(&sm.row[0]);

    sm.hist[tid] = 0u;
    if (tid == 0) mbar_init(mb, 1u);
    __syncthreads();

    int r = blockIdx.x;
    if (tid == 0 && r < rows)  // prologue prefetch
        { mbar_expect_tx(mb, ROWBYTES); bulk_g2s(rowa, x + (size_t)r * ROWLEN, ROWBYTES, mb); }
    uint32_t phase = 0;

    for (; r < rows; r += GRID) {
        mbar_wait(mb, phase); phase ^= 1;      // row r resident in smem

        // ==== selection: histogram refinement (bit space of positive floats) ====
        uint32_t lo = T0BITS, rng = 0xFFFFFFFFu;
        int shift = SHIFT1;
        uint32_t above = 0u;
        bool clamped = true, first = true;
        uint32_t Tb = 1u, quota = 0u;
        int tie_path = 0;

        for (;;) {
            // ---- histogram (reads row from smem) ----
            if (first) {
                // clamped full-range window: no upper-bound test needed
#pragma unroll
                for (int i = 0; i < 4; i++) {
                    float4 f = sm.row[tid + i * NT];
                    uint32_t b0 = (__float_as_uint(f.x) - T0BITS) >> SHIFT1;
                    uint32_t b1 = (__float_as_uint(f.y) - T0BITS) >> SHIFT1;
                    uint32_t b2 = (__float_as_uint(f.z) - T0BITS) >> SHIFT1;
                    uint32_t b3 = (__float_as_uint(f.w) - T0BITS) >> SHIFT1;
                    if (f.x >= 1.875f) atomicAdd(&sm.hist[b0 < NBIN - 1u ? b0 : NBIN - 1u], 1u);
                    if (f.y >= 1.875f) atomicAdd(&sm.hist[b1 < NBIN - 1u ? b1 : NBIN - 1u], 1u);
                    if (f.z >= 1.875f) atomicAdd(&sm.hist[b2 < NBIN - 1u ? b2 : NBIN - 1u], 1u);
                    if (f.w >= 1.875f) atomicAdd(&sm.hist[b3 < NBIN - 1u ? b3 : NBIN - 1u], 1u);
                }
            } else {
                const float lof = __uint_as_float(lo);
#pragma unroll
                for (int i = 0; i < 4; i++) {
                    float4 f = sm.row[tid + i * NT];
                    const float fv[4] = {f.x, f.y, f.z, f.w};
#pragma unroll
                    for (int e = 0; e < 4; e++) {
                        if (fv[e] >= lof) {
                            uint32_t d = __float_as_uint(fv[e]) - lo;
                            if (d < rng) {
                                uint32_t b = d >> shift;
                                if (b > NBIN - 1u) b = NBIN - 1u;
                                atomicAdd(&sm.hist[b], 1u);
                            }
                        }
                    }
                }
            }
            __syncthreads();                   // B1: histogram complete

            // ---- two-level suffix logic (bins descend as tid ascends) ----
            const int rb = NBIN - 1 - tid;
            const uint32_t h = sm.hist[rb];
            sm.hist[rb] = 0u;                  // re-zero for next use
            if (tid == 0) sm.bc[3] = 0u;
            const uint32_t wtot = __reduce_add_sync(0xFFFFFFFFu, h);
            if (lane == 0) sm.w[wid] = wtot;
            __syncthreads();                   // B2: warp totals ready

            // redundant per-warp scan of the 16 warp totals (no extra barrier)
            uint32_t t = (lane < NWARP) ? sm.w[lane] : 0u;
            uint32_t sc = t;
#pragma unroll
            for (int o = 1; o < 16; o <<= 1) {
                uint32_t u = __shfl_up_sync(0xFFFFFFFFu, sc, o);
                if (lane >= o) sc += u;
            }
            const uint32_t basew = (wid == 0) ? 0u
                                   : __shfl_sync(0xFFFFFFFFu, sc, wid - 1);
            const uint32_t total = __shfl_sync(0xFFFFFFFFu, sc, NWARP - 1);

            const uint32_t pre = above + basew;     // elems above my warp's bin range
            if (pre < KSEL && pre + wtot >= KSEL) { // crossing warp only (uniform)
                uint32_t incl = h;             // intra-warp suffix (bins desc w/ lane)
#pragma unroll
                for (int o = 1; o < 32; o <<= 1) {
                    uint32_t u = __shfl_up_sync(0xFFFFFFFFu, incl, o);
                    if (lane >= o) incl += u;
                }
                const uint32_t suf = pre + incl;
                if (suf >= KSEL && suf - h < KSEL) {
                    sm.bc[0] = (uint32_t)rb;
                    sm.bc[1] = suf - h;        // count(bits >= crossing-bin end)
                    sm.bc[2] = h;
                    sm.bc[3] = 1u;
                }
            }
            __syncthreads();                   // B3: crossing published

            if (sm.bc[3] == 0u) {
                if (first) {                   // count(>= t0) < K: search (0, t0)
                    above = total;
                    lo = 1u; rng = T0BITS - 1u; shift = 21;  // 512 bins x 2^21 >= t0 range
                    clamped = false; first = false;
                    continue;
                }
                Tb = 1u; tie_path = 0; break;  // <K positives: output = relu(x)
            }
            first = false;
            const uint32_t bstar = sm.bc[0];
            above = sm.bc[1];
            const uint32_t hb = sm.bc[2];
            const uint32_t rk = KSEL - above;  // rank within bin, 1 <= rk <= hb
            lo += bstar << shift;
            if (rk == hb) { Tb = lo; tie_path = 0; break; }   // whole bin => K
            if (shift == 0) { Tb = lo; quota = rk; tie_path = 1; break; }
            if (clamped && bstar == NBIN - 1u) {
                rng = 0xFFFFFFFFu; shift = 23; clamped = false;  // reopen clamp bin
            } else {
                rng = 1u << shift;
                shift = (shift > 9) ? (shift - 9) : 0;
                clamped = false;
            }
        }

        // ==== output (re-read row from smem, single HBM write) ====
        float4* __restrict__ ov = reinterpret_cast<float4*>(out + (size_t)r * ROWLEN);
        const float T = __uint_as_float(Tb);

        if (!tie_path) {
#pragma unroll
            for (int i = 0; i < 4; i++) {
                float4 f = sm.row[tid + i * NT];
                float4 o;
                o.x = (f.x >= T) ? f.x : 0.0f;
                o.y = (f.y >= T) ? f.y : 0.0f;
                o.z = (f.z >= T) ? f.z : 0.0f;
                o.w = (f.w >= T) ? f.w : 0.0f;
                ov[tid + i * NT] = o;
            }
        } else {
            // duplicates straddle rank K: keep `quota` lowest-index ties.
            // column(i,tid,e) = 4*(i*NT+tid)+e  => order (i, tid, e).
            // Two packed block scans rank ties per segment pair.
            uint32_t tc[4];
            float4 fr[4];
#pragma unroll
            for (int i = 0; i < 4; i++) {
                float4 f = sm.row[tid + i * NT];
                fr[i] = f;
                tc[i] = (f.x == T) + (f.y == T) + (f.z == T) + (f.w == T);
            }
            uint32_t packA = tc[0] | (tc[1] << 16);
            uint32_t packB = tc[2] | (tc[3] << 16);

            uint32_t inclA = packA, inclB = packB;
#pragma unroll
            for (int o = 1; o < 32; o <<= 1) {
                uint32_t uA = __shfl_up_sync(0xFFFFFFFFu, inclA, o);
                uint32_t uB = __shfl_up_sync(0xFFFFFFFFu, inclB, o);
                if (lane >= o) { inclA += uA; inclB += uB; }
            }
            if (lane == 31) { sm.w[wid] = inclA; sm.w[NWARP + wid] = inclB; }
            __syncthreads();
            uint32_t tA = (lane < NWARP) ? sm.w[lane] : 0u;
            uint32_t tB = (lane < NWARP) ? sm.w[NWARP + lane] : 0u;
            uint32_t sA = tA, sB = tB;
#pragma unroll
            for (int o = 1; o < 16; o <<= 1) {
                uint32_t uA = __shfl_up_sync(0xFFFFFFFFu, sA, o);
                uint32_t uB = __shfl_up_sync(0xFFFFFFFFu, sB, o);
                if (lane >= o) { sA += uA; sB += uB; }
            }
            uint32_t baseA = (wid == 0) ? 0u : __shfl_sync(0xFFFFFFFFu, sA, wid - 1);
            uint32_t baseB = (wid == 0) ? 0u : __shfl_sync(0xFFFFFFFFu, sB, wid - 1);
            uint32_t totA  = __shfl_sync(0xFFFFFFFFu, sA, NWARP - 1);
            uint32_t totB  = __shfl_sync(0xFFFFFFFFu, sB, NWARP - 1);

            const uint32_t exclA = baseA + inclA - packA;   // per-seg excl (packed)
            const uint32_t exclB = baseB + inclB - packB;
            const uint32_t tot0 = totA & 0xFFFFu;
            const uint32_t tot1 = totA >> 16;
            const uint32_t tot2 = totB & 0xFFFFu;

            uint32_t rank[4];
            rank[0] = exclA & 0xFFFFu;
            rank[1] = tot0 + (exclA >> 16);
            rank[2] = tot0 + tot1 + (exclB & 0xFFFFu);
            rank[3] = tot0 + tot1 + tot2 + (exclB >> 16);

#pragma unroll
            for (int i = 0; i < 4; i++) {
                float4 f = fr[i];
                float4 o; uint32_t rk2 = rank[i];
                o.x = (f.x > T) ? f.x : ((f.x == T && rk2++ < quota) ? f.x : 0.0f);
                o.y = (f.y > T) ? f.y : ((f.y == T && rk2++ < quota) ? f.y : 0.0f);
                o.z = (f.z > T) ? f.z : ((f.z == T && rk2++ < quota) ? f.z : 0.0f);
                o.w = (f.w > T) ? f.w : ((f.w == T && rk2++ < quota) ? f.w : 0.0f);
                ov[tid + i * NT] = o;
            }
        }

        __syncthreads();                       // B4: all row reads done -> buffer free
        if (tid == 0) {                        // prefetch row r+GRID
            int rn = r + GRID;
            if (rn < rows) {
                mbar_expect_tx(mb, ROWBYTES);
                bulk_g2s(rowa, x + (size_t)rn * ROWLEN, ROWBYTES, mb);
            }
        }
    }
}

extern "C" void kernel_launch(void* const* d_in, const int* in_sizes, int n_in,
                              void* d_out, int out_size) {
    const float* x = (const float*)d_in[0];
    float* out = (float*)d_out;
    int rows = in_sizes[0] / ROWLEN;
    int grid = (rows < GRID) ? rows : GRID;
    topk_relu_kernel<<<grid, NT>>>(x, out, rows);
}

// round 12
// speedup vs baseline: 1.4319x; 1.1221x over previous
#include <cuda_runtime.h>
#include <stdint.h>

#define ROWLEN   8192
#define NT       512
#define NPT      16             // ROWLEN / NT
#define NWARP    16
#define KSEL     128
#define NBIN     512            // one bin per thread
#define T0BITS   0x3FF00000u    // 1.875f: count(x>=t0) ~ 249 +/- 16 per N(0,1) row
#define SHIFT1   12             // primary bins: width 2^12 ulps (512 bins cover 2^21)
#define ROWBYTES (ROWLEN * 4)
#define GRID     608            // persistent CTAs (4 per SM x 152 SMs)

__device__ unsigned int g_row_ctr;                 // dynamic row queue head

__global__ void reset_ctr_kernel() { g_row_ctr = 0u; }

__device__ __forceinline__ uint32_t smem_u32(const void* p) {
    uint32_t a;
    asm("{ .reg .u64 t; cvta.to.shared.u64 t, %1; cvt.u32.u64 %0, t; }"
        : "=r"(a) : "l"(p));
    return a;
}
__device__ __forceinline__ void mbar_init(uint32_t m, uint32_t c) {
    asm volatile("mbarrier.init.shared.b64 [%0], %1;" :: "r"(m), "r"(c) : "memory");
}
__device__ __forceinline__ void mbar_expect_tx(uint32_t m, uint32_t bytes) {
    asm volatile("mbarrier.arrive.expect_tx.shared.b64 _, [%0], %1;"
                 :: "r"(m), "r"(bytes) : "memory");
}
__device__ __forceinline__ void bulk_g2s(uint32_t dst, const void* src,
                                         uint32_t bytes, uint32_t m) {
    asm volatile("cp.async.bulk.shared::cluster.global.mbarrier::complete_tx::bytes "
                 "[%0], [%1], %2, [%3];"
                 :: "r"(dst), "l"(src), "r"(bytes), "r"(m) : "memory");
}
__device__ __forceinline__ void mbar_wait(uint32_t m, uint32_t ph) {
    uint32_t done;
    do {
        asm volatile("{ .reg .pred p; "
                     "mbarrier.try_wait.parity.acquire.cta.shared::cta.b64 p, [%1], %2; "
                     "selp.b32 %0, 1, 0, p; }"
                     : "=r"(done) : "r"(m), "r"(ph) : "memory");
    } while (!done);
}

struct SMem {
    float4   row[ROWLEN / 4];       // 32 KB staged row (row data lives here, not regs)
    uint32_t hist[NBIN];            // 2 KB
    uint32_t w[2 * NWARP];          // scan scratch (two packed scans in tie path)
    uint32_t bc[4];                 // 0=bstar 1=above_new 2=h 3=found
    uint32_t rnext;                 // next row id (published pre-B4)
    unsigned long long mbar;
};

// Persistent per-row top-K of relu(x). 4 CTAs/SM; rows claimed from a global
// atomic queue so no CTA strands a remainder row (tail ~= 1 row). Row data
// stays in SMEM (re-read per phase) to keep regs <= 32 at 4x512 occupancy.
// Selection = pre-filtered (t0=1.875) 512-bin histogram refinement in
// positive-float bit space; exact for any input. Threshold ties broken by
// LOWEST COLUMN INDEX (jax.lax.top_k rule) via deterministic block scans.
__global__ __launch_bounds__(NT, 4)
void topk_relu_kernel(const float* __restrict__ x, float* __restrict__ out,
                      int rows) {
    __shared__ SMem sm;
    const int tid  = threadIdx.x;
    const int wid  = tid >> 5;
    const int lane = tid & 31;

    const uint32_t mb   = smem_u32(&sm.mbar);
    const uint32_t rowa = smem_u32(&sm.row[0]);

    sm.hist[tid] = 0u;
    if (tid == 0) {
        mbar_init(mb, 1u);
        uint32_t r0 = atomicAdd(&g_row_ctr, 1u);   // claim first row
        sm.rnext = r0;
        if (r0 < (uint32_t)rows)
            { mbar_expect_tx(mb, ROWBYTES); bulk_g2s(rowa, x + (size_t)r0 * ROWLEN, ROWBYTES, mb); }
    }
    __syncthreads();

    uint32_t phase = 0;
    int r = (int)sm.rnext;

    while (r < rows) {
        mbar_wait(mb, phase); phase ^= 1;      // row r resident in smem

        // ==== selection: histogram refinement (bit space of positive floats) ====
        uint32_t lo = T0BITS, rng = 0xFFFFFFFFu;
        int shift = SHIFT1;
        uint32_t above = 0u;
        bool clamped = true, first = true;
        uint32_t Tb = 1u, quota = 0u;
        int tie_path = 0;

        for (;;) {
            // ---- histogram (reads row from smem) ----
            if (first) {
                // clamped full-range window: no upper-bound test needed
#pragma unroll
                for (int i = 0; i < 4; i++) {
                    float4 f = sm.row[tid + i * NT];
                    uint32_t b0 = (__float_as_uint(f.x) - T0BITS) >> SHIFT1;
                    uint32_t b1 = (__float_as_uint(f.y) - T0BITS) >> SHIFT1;
                    uint32_t b2 = (__float_as_uint(f.z) - T0BITS) >> SHIFT1;
                    uint32_t b3 = (__float_as_uint(f.w) - T0BITS) >> SHIFT1;
                    if (f.x >= 1.875f) atomicAdd(&sm.hist[b0 < NBIN - 1u ? b0 : NBIN - 1u], 1u);
                    if (f.y >= 1.875f) atomicAdd(&sm.hist[b1 < NBIN - 1u ? b1 : NBIN - 1u], 1u);
                    if (f.z >= 1.875f) atomicAdd(&sm.hist[b2 < NBIN - 1u ? b2 : NBIN - 1u], 1u);
                    if (f.w >= 1.875f) atomicAdd(&sm.hist[b3 < NBIN - 1u ? b3 : NBIN - 1u], 1u);
                }
            } else {
                const float lof = __uint_as_float(lo);
#pragma unroll
                for (int i = 0; i < 4; i++) {
                    float4 f = sm.row[tid + i * NT];
                    const float fv[4] = {f.x, f.y, f.z, f.w};
#pragma unroll
                    for (int e = 0; e < 4; e++) {
                        if (fv[e] >= lof) {
                            uint32_t d = __float_as_uint(fv[e]) - lo;
                            if (d < rng) {
                                uint32_t b = d >> shift;
                                if (b > NBIN - 1u) b = NBIN - 1u;
                                atomicAdd(&sm.hist[b], 1u);
                            }
                        }
                    }
                }
            }
            __syncthreads();                   // B1: histogram complete

            // ---- two-level suffix logic (bins descend as tid ascends) ----
            const int rb = NBIN - 1 - tid;
            const uint32_t h = sm.hist[rb];
            sm.hist[rb] = 0u;                  // re-zero for next use
            if (tid == 0) sm.bc[3] = 0u;
            const uint32_t wtot = __reduce_add_sync(0xFFFFFFFFu, h);
            if (lane == 0) sm.w[wid] = wtot;
            __syncthreads();                   // B2: warp totals ready

            // redundant per-warp scan of the 16 warp totals (no extra barrier)
            uint32_t t = (lane < NWARP) ? sm.w[lane] : 0u;
            uint32_t sc = t;
#pragma unroll
            for (int o = 1; o < 16; o <<= 1) {
                uint32_t u = __shfl_up_sync(0xFFFFFFFFu, sc, o);
                if (lane >= o) sc += u;
            }
            const uint32_t basew = (wid == 0) ? 0u
                                   : __shfl_sync(0xFFFFFFFFu, sc, wid - 1);
            const uint32_t total = __shfl_sync(0xFFFFFFFFu, sc, NWARP - 1);

            const uint32_t pre = above + basew;     // elems above my warp's bin range
            if (pre < KSEL && pre + wtot >= KSEL) { // crossing warp only (uniform)
                uint32_t incl = h;             // intra-warp suffix (bins desc w/ lane)
#pragma unroll
                for (int o = 1; o < 32; o <<= 1) {
                    uint32_t u = __shfl_up_sync(0xFFFFFFFFu, incl, o);
                    if (lane >= o) incl += u;
                }
                const uint32_t suf = pre + incl;
                if (suf >= KSEL && suf - h < KSEL) {
                    sm.bc[0] = (uint32_t)rb;
                    sm.bc[1] = suf - h;        // count(bits >= crossing-bin end)
                    sm.bc[2] = h;
                    sm.bc[3] = 1u;
                }
            }
            __syncthreads();                   // B3: crossing published

            if (sm.bc[3] == 0u) {
                if (first) {                   // count(>= t0) < K: search (0, t0)
                    above = total;
                    lo = 1u; rng = T0BITS - 1u; shift = 21;  // 512 bins x 2^21 >= t0 range
                    clamped = false; first = false;
                    continue;
                }
                Tb = 1u; tie_path = 0; break;  // <K positives: output = relu(x)
            }
            first = false;
            const uint32_t bstar = sm.bc[0];
            above = sm.bc[1];
            const uint32_t hb = sm.bc[2];
            const uint32_t rk = KSEL - above;  // rank within bin, 1 <= rk <= hb
            lo += bstar << shift;
            if (rk == hb) { Tb = lo; tie_path = 0; break; }   // whole bin => K
            if (shift == 0) { Tb = lo; quota = rk; tie_path = 1; break; }
            if (clamped && bstar == NBIN - 1u) {
                rng = 0xFFFFFFFFu; shift = 23; clamped = false;  // reopen clamp bin
            } else {
                rng = 1u << shift;
                shift = (shift > 9) ? (shift - 9) : 0;
                clamped = false;
            }
        }

        // ==== output (re-read row from smem, single HBM write) ====
        float4* __restrict__ ov = reinterpret_cast<float4*>(out + (size_t)r * ROWLEN);
        const float T = __uint_as_float(Tb);

        if (!tie_path) {
#pragma unroll
            for (int i = 0; i < 4; i++) {
                float4 f = sm.row[tid + i * NT];
                float4 o;
                o.x = (f.x >= T) ? f.x : 0.0f;
                o.y = (f.y >= T) ? f.y : 0.0f;
                o.z = (f.z >= T) ? f.z : 0.0f;
                o.w = (f.w >= T) ? f.w : 0.0f;
                ov[tid + i * NT] = o;
            }
        } else {
            // duplicates straddle rank K: keep `quota` lowest-index ties.
            // column(i,tid,e) = 4*(i*NT+tid)+e  => order (i, tid, e).
            uint32_t tc[4];
            float4 fr[4];
#pragma unroll
            for (int i = 0; i < 4; i++) {
                float4 f = sm.row[tid + i * NT];
                fr[i] = f;
                tc[i] = (f.x == T) + (f.y == T) + (f.z == T) + (f.w == T);
            }
            uint32_t packA = tc[0] | (tc[1] << 16);
            uint32_t packB = tc[2] | (tc[3] << 16);

            uint32_t inclA = packA, inclB = packB;
#pragma unroll
            for (int o = 1; o < 32; o <<= 1) {
                uint32_t uA = __shfl_up_sync(0xFFFFFFFFu, inclA, o);
                uint32_t uB = __shfl_up_sync(0xFFFFFFFFu, inclB, o);
                if (lane >= o) { inclA += uA; inclB += uB; }
            }
            if (lane == 31) { sm.w[wid] = inclA; sm.w[NWARP + wid] = inclB; }
            __syncthreads();
            uint32_t tA = (lane < NWARP) ? sm.w[lane] : 0u;
            uint32_t tB = (lane < NWARP) ? sm.w[NWARP + lane] : 0u;
            uint32_t sA = tA, sB = tB;
#pragma unroll
            for (int o = 1; o < 16; o <<= 1) {
                uint32_t uA = __shfl_up_sync(0xFFFFFFFFu, sA, o);
                uint32_t uB = __shfl_up_sync(0xFFFFFFFFu, sB, o);
                if (lane >= o) { sA += uA; sB += uB; }
            }
            uint32_t baseA = (wid == 0) ? 0u : __shfl_sync(0xFFFFFFFFu, sA, wid - 1);
            uint32_t baseB = (wid == 0) ? 0u : __shfl_sync(0xFFFFFFFFu, sB, wid - 1);
            uint32_t totA  = __shfl_sync(0xFFFFFFFFu, sA, NWARP - 1);
            uint32_t totB  = __shfl_sync(0xFFFFFFFFu, sB, NWARP - 1);

            const uint32_t exclA = baseA + inclA - packA;
            const uint32_t exclB = baseB + inclB - packB;
            const uint32_t tot0 = totA & 0xFFFFu;
            const uint32_t tot1 = totA >> 16;
            const uint32_t tot2 = totB & 0xFFFFu;

            uint32_t rank[4];
            rank[0] = exclA & 0xFFFFu;
            rank[1] = tot0 + (exclA >> 16);
            rank[2] = tot0 + tot1 + (exclB & 0xFFFFu);
            rank[3] = tot0 + tot1 + tot2 + (exclB >> 16);

#pragma unroll
            for (int i = 0; i < 4; i++) {
                float4 f = fr[i];
                float4 o; uint32_t rk2 = rank[i];
                o.x = (f.x > T) ? f.x : ((f.x == T && rk2++ < quota) ? f.x : 0.0f);
                o.y = (f.y > T) ? f.y : ((f.y == T && rk2++ < quota) ? f.y : 0.0f);
                o.z = (f.z > T) ? f.z : ((f.z == T && rk2++ < quota) ? f.z : 0.0f);
                o.w = (f.w > T) ? f.w : ((f.w == T && rk2++ < quota) ? f.w : 0.0f);
                ov[tid + i * NT] = o;
            }
        }

        if (tid == 0) sm.rnext = atomicAdd(&g_row_ctr, 1u);  // claim next row
        __syncthreads();                       // B4: row reads done + rnext visible
        r = (int)sm.rnext;
        if (tid == 0 && r < rows) {            // prefetch claimed row
            mbar_expect_tx(mb, ROWBYTES);
            bulk_g2s(rowa, x + (size_t)r * ROWLEN, ROWBYTES, mb);
        }
    }
}

extern "C" void kernel_launch(void* const* d_in, const int* in_sizes, int n_in,
                              void* d_out, int out_size) {
    const float* x = (const float*)d_in[0];
    float* out = (float*)d_out;
    int rows = in_sizes[0] / ROWLEN;
    int grid = (rows < GRID) ? rows : GRID;
    reset_ctr_kernel<<<1, 1>>>();
    topk_relu_kernel<<<grid, NT>>>(x, out, rows);
}